// round 7
// baseline (speedup 1.0000x reference)
#include <cuda_runtime.h>
#include <math.h>

#define NM      4096
#define NPTS    131072
#define GRES    16

typedef unsigned long long u64;

// ---- scratch (no allocations allowed) ----
__device__ int g_cnt[NM];      // zero at load; re-zeroed by k_mlp each call
__device__ int g_off[NM];
__device__ int g_start[NM];
__device__ int g_vox[NPTS];
__device__ int g_sorted[NPTS];

__global__ void k_index(const float* __restrict__ pts) {
    int n = blockIdx.x * blockDim.x + threadIdx.x;
    if (n >= NPTS) return;
    float x = pts[3 * n + 0], y = pts[3 * n + 1], z = pts[3 * n + 2];
    int ix = (int)fminf(fmaxf(x * (float)GRES, 0.f), (float)(GRES - 1));
    int iy = (int)fminf(fmaxf(y * (float)GRES, 0.f), (float)(GRES - 1));
    int iz = (int)fminf(fmaxf(z * (float)GRES, 0.f), (float)(GRES - 1));
    int v = ix * (GRES * GRES) + iy * GRES + iz;
    g_vox[n] = v;
    atomicAdd(&g_cnt[v], 1);
}

__global__ void k_scan() {
    __shared__ int sh[1024];
    int t = threadIdx.x;
    int c0 = g_cnt[4 * t + 0], c1 = g_cnt[4 * t + 1];
    int c2 = g_cnt[4 * t + 2], c3 = g_cnt[4 * t + 3];
    int s = c0 + c1 + c2 + c3;
    sh[t] = s;
    __syncthreads();
    for (int d = 1; d < 1024; d <<= 1) {
        int v = (t >= d) ? sh[t - d] : 0;
        __syncthreads();
        sh[t] += v;
        __syncthreads();
    }
    int excl = sh[t] - s;
    g_start[4 * t + 0] = excl; g_off[4 * t + 0] = excl; excl += c0;
    g_start[4 * t + 1] = excl; g_off[4 * t + 1] = excl; excl += c1;
    g_start[4 * t + 2] = excl; g_off[4 * t + 2] = excl; excl += c2;
    g_start[4 * t + 3] = excl; g_off[4 * t + 3] = excl;
}

__global__ void k_scatter() {
    int n = blockIdx.x * blockDim.x + threadIdx.x;
    if (n >= NPTS) return;
    int v = g_vox[n];
    int pos = atomicAdd(&g_off[v], 1);
    g_sorted[pos] = n;
}

// ---- packed fp32x2 helpers ----
__device__ __forceinline__ u64 f2fma(u64 a, u64 b, u64 c) {
    u64 d;
    asm("fma.rn.f32x2 %0, %1, %2, %3;" : "=l"(d) : "l"(a), "l"(b), "l"(c));
    return d;
}
__device__ __forceinline__ u64 f2add(u64 a, u64 b) {
    u64 d;
    asm("add.rn.f32x2 %0, %1, %2;" : "=l"(d) : "l"(a), "l"(b));
    return d;
}
__device__ __forceinline__ u64 pk2(float v) {
    u64 r;
    asm("mov.b64 %0, {%1, %1};" : "=l"(r) : "f"(v));
    return r;
}
__device__ __forceinline__ float2 unpk(u64 p) {
    float2 f;
    asm("mov.b64 {%0, %1}, %2;" : "=f"(f.x), "=f"(f.y) : "l"(p));
    return f;
}
__device__ __forceinline__ void accP(u64* P, const float* wrow, u64 v2) {
    const ulonglong2* w = reinterpret_cast<const ulonglong2*>(wrow);
#pragma unroll
    for (int j = 0; j < 8; j++) {
        ulonglong2 ww = w[j];
        P[2 * j + 0] = f2fma(v2, ww.x, P[2 * j + 0]);
        P[2 * j + 1] = f2fma(v2, ww.y, P[2 * j + 1]);
    }
}
__device__ __forceinline__ void loadP(u64* P, const float* s) {
    const ulonglong2* b = reinterpret_cast<const ulonglong2*>(s);
#pragma unroll
    for (int j = 0; j < 8; j++) {
        ulonglong2 v = b[j];
        P[2 * j + 0] = v.x;
        P[2 * j + 1] = v.y;
    }
}
__device__ __forceinline__ void zeroP(u64* P) {
#pragma unroll
    for (int j = 0; j < 16; j++) P[j] = 0ull;
}
__device__ __forceinline__ void unpackRelu(const u64* P, float* H) {
#pragma unroll
    for (int j = 0; j < 16; j++) {
        float2 f = unpk(P[j]);
        H[2 * j + 0] = fmaxf(f.x, 0.f);
        H[2 * j + 1] = fmaxf(f.y, 0.f);
    }
}
__device__ __forceinline__ void unpackPlain(const u64* P, float* H) {
#pragma unroll
    for (int j = 0; j < 16; j++) {
        float2 f = unpk(P[j]);
        H[2 * j + 0] = f.x;
        H[2 * j + 1] = f.y;
    }
}

// cross-warp partial-sum exchange: warp1 posts partial, warp0 adds & posts sum
__device__ __forceinline__ void exchangeP(u64* P, u64* buf, int warp, int lane) {
    if (warp == 1) {
#pragma unroll
        for (int j = 0; j < 16; j++) buf[j * 32 + lane] = P[j];
    }
    __syncthreads();
    if (warp == 0) {
#pragma unroll
        for (int j = 0; j < 16; j++) {
            P[j] = f2add(P[j], buf[j * 32 + lane]);
            buf[j * 32 + lane] = P[j];
        }
    }
    __syncthreads();
    if (warp == 1) {
#pragma unroll
        for (int j = 0; j < 16; j++) P[j] = buf[j * 32 + lane];
    }
}

// ---- staging in 8-row chunks (tmp needs <= 504 floats) ----
__device__ __forceinline__ void stage_odd(const float* g, float* T, float* tmp,
                                          int tid, int C) {
#pragma unroll
    for (int h = 0; h < 4; h++) {
        const float4* g4 = reinterpret_cast<const float4*>(g + h * 8 * C);
        float4* t4 = reinterpret_cast<float4*>(tmp);
        int n4 = (8 * C) >> 2;
        for (int i = tid; i < n4; i += 64) t4[i] = g4[i];
        __syncthreads();
        for (int i = tid; i < 8 * C; i += 64) {
            int d = i >> 3, o = i & 7;
            T[d * 32 + h * 8 + o] = tmp[o * C + d];
        }
        __syncthreads();
    }
}
__device__ __forceinline__ void stage32(const float* g, float* T, float* tmp,
                                        int tid) {
#pragma unroll
    for (int h = 0; h < 4; h++) {
        const float* gh = g + h * 256;
        for (int i = tid; i < 256; i += 64)
            tmp[(i >> 5) * 33 + (i & 31)] = gh[i];
        __syncthreads();
        for (int i = tid; i < 256; i += 64) {
            int d = i >> 3, o = i & 7;
            T[d * 32 + h * 8 + o] = tmp[o * 33 + d];
        }
        __syncthreads();
    }
}

// smem pool layout (floats)
#define OFF_W0T  0
#define OFF_W1T  2016
#define OFF_FT   3040
#define OFF_VT   4064
#define OFF_SM   5952
#define OFF_XBUF 6216      // 1024 floats: exchange buffer, overlaid on staging tmp
#define SP_TOT   7240      // 28960 bytes

__global__ void __launch_bounds__(64, 7) k_mlp(
    const float* __restrict__ pts, const float* __restrict__ vdirs,
    const float* __restrict__ w0, const float* __restrict__ b0,
    const float* __restrict__ w1, const float* __restrict__ b1,
    const float* __restrict__ fw, const float* __restrict__ fb,
    const float* __restrict__ sw, const float* __restrict__ sb,
    const float* __restrict__ vw, const float* __restrict__ vb,
    const float* __restrict__ rw, const float* __restrict__ rb,
    float* __restrict__ out)
{
    const int vox = blockIdx.x;
    const int tid = threadIdx.x;

    __shared__ __align__(16) float sp[SP_TOT];
    float* s_w0T = sp + OFF_W0T;   // [d=63][o=32]
    float* s_w1T = sp + OFF_W1T;   // [d=32][o=32]
    float* s_fT  = sp + OFF_FT;    // [d=32][o=32]
    float* s_vT  = sp + OFF_VT;    // [d=59][o=32]
    float* s_sm  = sp + OFF_SM;
    float* s_tmp = sp + OFF_XBUF;
    u64*   xbuf  = reinterpret_cast<u64*>(sp + OFF_XBUF);

    const int start = g_start[vox];
    const int count = g_cnt[vox];

    stage_odd(w0 + (size_t)vox * 2016, s_w0T, s_tmp, tid, 63);
    stage32(w1 + (size_t)vox * 1024, s_w1T, s_tmp, tid);
    stage32(fw + (size_t)vox * 1024, s_fT, s_tmp, tid);
    stage_odd(vw + (size_t)vox * 1888, s_vT, s_tmp, tid, 59);

    for (int i = tid; i < 96; i += 64) {
        int c = i >> 5, d = i & 31;
        s_sm[160 + d * 3 + c] = rw[(size_t)vox * 96 + i];
    }
    if (tid < 32) {
        s_sm[tid]       = sw[(size_t)vox * 32 + tid];
        s_sm[32 + tid]  = b0[(size_t)vox * 32 + tid];
        s_sm[64 + tid]  = b1[(size_t)vox * 32 + tid];
        s_sm[96 + tid]  = fb[(size_t)vox * 32 + tid];
        s_sm[128 + tid] = vb[(size_t)vox * 32 + tid];
    }
    if (tid < 3) s_sm[256 + tid] = rb[(size_t)vox * 3 + tid];
    if (tid == 0) {
        s_sm[259] = sb[vox];
        g_cnt[vox] = 0;   // reset for next replay (count already read above)
    }
    __syncthreads();

    const int warp = tid >> 5, lane = tid & 31;

    // both warps cooperate on each 32-point tile, splitting the d-dimension
    for (int base = 0; base < count; base += 32) {
        const int i = base + lane;
        const bool act = (i < count);
        int n = 0;
        float px = 0.f, py = 0.f, pz = 0.f, dvx = 0.f, dvy = 0.f, dvz = 0.f;
        if (act) {
            n = g_sorted[start + i];
            px = pts[3 * n + 0]; py = pts[3 * n + 1]; pz = pts[3 * n + 2];
            int ray = n >> 7;   // N_SAMPLES = 128
            dvx = vdirs[3 * ray + 0]; dvy = vdirs[3 * ray + 1]; dvz = vdirs[3 * ray + 2];
        }

        u64 P[16];
        float A[32], B[32];

        // ---- layer0: 63 -> 32 (warp0: bias,xyz,k=0..4; warp1: k=5..9) ----
        {
            float sx = __sinf(px), cx = __cosf(px);
            float sy = __sinf(py), cy = __cosf(py);
            float sz = __sinf(pz), cz = __cosf(pz);
            if (warp == 0) {
                loadP(P, s_sm + 32);
                accP(P, s_w0T + 0 * 32, pk2(px));
                accP(P, s_w0T + 1 * 32, pk2(py));
                accP(P, s_w0T + 2 * 32, pk2(pz));
#pragma unroll
                for (int k = 0; k < 5; k++) {
                    const float* r = s_w0T + (3 + 6 * k) * 32;
                    accP(P, r + 0 * 32, pk2(sx));
                    accP(P, r + 1 * 32, pk2(sy));
                    accP(P, r + 2 * 32, pk2(sz));
                    accP(P, r + 3 * 32, pk2(cx));
                    accP(P, r + 4 * 32, pk2(cy));
                    accP(P, r + 5 * 32, pk2(cz));
                    float t;
                    t = 2.f * sx * cx; cx = 1.f - 2.f * sx * sx; sx = t;
                    t = 2.f * sy * cy; cy = 1.f - 2.f * sy * sy; sy = t;
                    t = 2.f * sz * cz; cz = 1.f - 2.f * sz * sz; sz = t;
                }
            } else {
                zeroP(P);
                // advance recurrence silently to k=5 (numerically identical to R6)
#pragma unroll
                for (int k = 0; k < 5; k++) {
                    float t;
                    t = 2.f * sx * cx; cx = 1.f - 2.f * sx * sx; sx = t;
                    t = 2.f * sy * cy; cy = 1.f - 2.f * sy * sy; sy = t;
                    t = 2.f * sz * cz; cz = 1.f - 2.f * sz * sz; sz = t;
                }
#pragma unroll
                for (int k = 5; k < 10; k++) {
                    const float* r = s_w0T + (3 + 6 * k) * 32;
                    accP(P, r + 0 * 32, pk2(sx));
                    accP(P, r + 1 * 32, pk2(sy));
                    accP(P, r + 2 * 32, pk2(sz));
                    accP(P, r + 3 * 32, pk2(cx));
                    accP(P, r + 4 * 32, pk2(cy));
                    accP(P, r + 5 * 32, pk2(cz));
                    float t;
                    t = 2.f * sx * cx; cx = 1.f - 2.f * sx * sx; sx = t;
                    t = 2.f * sy * cy; cy = 1.f - 2.f * sy * sy; sy = t;
                    t = 2.f * sz * cz; cz = 1.f - 2.f * sz * sz; sz = t;
                }
            }
        }
        exchangeP(P, xbuf, warp, lane);
        unpackRelu(P, A);

        // ---- layer1: 32 -> 32 (warp0: bias + d0..15; warp1: d16..31) ----
        if (warp == 0) {
            loadP(P, s_sm + 64);
#pragma unroll
            for (int d = 0; d < 16; d++) accP(P, s_w1T + d * 32, pk2(A[d]));
        } else {
            zeroP(P);
#pragma unroll
            for (int d = 16; d < 32; d++) accP(P, s_w1T + d * 32, pk2(A[d]));
        }
        exchangeP(P, xbuf, warp, lane);
        unpackRelu(P, B);

        // ---- sigma: 32 -> 1 (warp1 only) ----
        float sg = 0.f;
        if (warp == 1) {
            sg = s_sm[259];
#pragma unroll
            for (int d = 0; d < 32; d++) sg = fmaf(B[d], s_sm[d], sg);
        }

        // ---- feat: 32 -> 32, no relu (split d) ----
        if (warp == 0) {
            loadP(P, s_sm + 96);
#pragma unroll
            for (int d = 0; d < 16; d++) accP(P, s_fT + d * 32, pk2(B[d]));
        } else {
            zeroP(P);
#pragma unroll
            for (int d = 16; d < 32; d++) accP(P, s_fT + d * 32, pk2(B[d]));
        }
        exchangeP(P, xbuf, warp, lane);
        unpackPlain(P, A);

        // ---- view: 59 -> 32 (warp0: bias + A[0..29]; warp1: rest) ----
        if (warp == 0) {
            loadP(P, s_sm + 128);
#pragma unroll
            for (int d = 0; d < 30; d++) accP(P, s_vT + d * 32, pk2(A[d]));
        } else {
            zeroP(P);
            accP(P, s_vT + 30 * 32, pk2(A[30]));
            accP(P, s_vT + 31 * 32, pk2(A[31]));
            accP(P, s_vT + 32 * 32, pk2(dvx));
            accP(P, s_vT + 33 * 32, pk2(dvy));
            accP(P, s_vT + 34 * 32, pk2(dvz));
            float sx = __sinf(dvx), cx = __cosf(dvx);
            float sy = __sinf(dvy), cy = __cosf(dvy);
            float sz = __sinf(dvz), cz = __cosf(dvz);
#pragma unroll
            for (int k = 0; k < 4; k++) {
                const float* r = s_vT + (35 + 6 * k) * 32;
                accP(P, r + 0 * 32, pk2(sx));
                accP(P, r + 1 * 32, pk2(sy));
                accP(P, r + 2 * 32, pk2(sz));
                accP(P, r + 3 * 32, pk2(cx));
                accP(P, r + 4 * 32, pk2(cy));
                accP(P, r + 5 * 32, pk2(cz));
                float t;
                t = 2.f * sx * cx; cx = 1.f - 2.f * sx * sx; sx = t;
                t = 2.f * sy * cy; cy = 1.f - 2.f * sy * sy; sy = t;
                t = 2.f * sz * cz; cz = 1.f - 2.f * sz * sz; sz = t;
            }
        }
        exchangeP(P, xbuf, warp, lane);
        unpackRelu(P, B);

        // ---- rgb: warp0 computes ch0,ch1; warp1 ch2 (+stores sigma) ----
        if (warp == 0) {
            float r0 = s_sm[256], r1 = s_sm[257];
#pragma unroll
            for (int d = 0; d < 32; d++) {
                r0 = fmaf(B[d], s_sm[160 + d * 3 + 0], r0);
                r1 = fmaf(B[d], s_sm[160 + d * 3 + 1], r1);
            }
            if (act) {
                out[3 * n + 0] = r0;
                out[3 * n + 1] = r1;
            }
        } else {
            float r2 = s_sm[258];
#pragma unroll
            for (int d = 0; d < 32; d++)
                r2 = fmaf(B[d], s_sm[160 + d * 3 + 2], r2);
            if (act) {
                out[3 * n + 2] = r2;
                out[(size_t)NPTS * 3 + n] = sg;
            }
        }
    }
}

extern "C" void kernel_launch(void* const* d_in, const int* in_sizes, int n_in,
                              void* d_out, int out_size) {
    (void)in_sizes; (void)n_in; (void)out_size;
    const float* pts = (const float*)d_in[0];
    const float* vd  = (const float*)d_in[1];
    const float* w0  = (const float*)d_in[2];
    const float* b0  = (const float*)d_in[3];
    const float* w1  = (const float*)d_in[4];
    const float* b1  = (const float*)d_in[5];
    const float* fw  = (const float*)d_in[6];
    const float* fb  = (const float*)d_in[7];
    const float* sw  = (const float*)d_in[8];
    const float* sb  = (const float*)d_in[9];
    const float* vw  = (const float*)d_in[10];
    const float* vb  = (const float*)d_in[11];
    const float* rw  = (const float*)d_in[12];
    const float* rb  = (const float*)d_in[13];

    k_index<<<512, 256>>>(pts);
    k_scan<<<1, 1024>>>();
    k_scatter<<<512, 256>>>();
    k_mlp<<<NM, 64>>>(pts, vd, w0, b0, w1, b1, fw, fb, sw, sb, vw, vb, rw, rb,
                      (float*)d_out);
}

// round 8
// speedup vs baseline: 1.4710x; 1.4710x over previous
#include <cuda_runtime.h>
#include <math.h>

#define NM      4096
#define NPTS    131072
#define GRES    16

typedef unsigned long long u64;

// ---- scratch (no allocations allowed) ----
__device__ int g_cnt[NM];      // zero at load; re-zeroed by k_mlp each call
__device__ int g_off[NM];
__device__ int g_start[NM];
__device__ int g_vox[NPTS];
__device__ int g_sorted[NPTS];

__global__ void k_index(const float* __restrict__ pts) {
    int n = blockIdx.x * blockDim.x + threadIdx.x;
    if (n >= NPTS) return;
    float x = pts[3 * n + 0], y = pts[3 * n + 1], z = pts[3 * n + 2];
    int ix = (int)fminf(fmaxf(x * (float)GRES, 0.f), (float)(GRES - 1));
    int iy = (int)fminf(fmaxf(y * (float)GRES, 0.f), (float)(GRES - 1));
    int iz = (int)fminf(fmaxf(z * (float)GRES, 0.f), (float)(GRES - 1));
    int v = ix * (GRES * GRES) + iy * GRES + iz;
    g_vox[n] = v;
    atomicAdd(&g_cnt[v], 1);
}

// one block, 1024 threads, 4 bins each
__global__ void k_scan() {
    __shared__ int sh[1024];
    int t = threadIdx.x;
    int c0 = g_cnt[4 * t + 0], c1 = g_cnt[4 * t + 1];
    int c2 = g_cnt[4 * t + 2], c3 = g_cnt[4 * t + 3];
    int s = c0 + c1 + c2 + c3;
    sh[t] = s;
    __syncthreads();
    for (int d = 1; d < 1024; d <<= 1) {
        int v = (t >= d) ? sh[t - d] : 0;
        __syncthreads();
        sh[t] += v;
        __syncthreads();
    }
    int excl = sh[t] - s;
    g_start[4 * t + 0] = excl; g_off[4 * t + 0] = excl; excl += c0;
    g_start[4 * t + 1] = excl; g_off[4 * t + 1] = excl; excl += c1;
    g_start[4 * t + 2] = excl; g_off[4 * t + 2] = excl; excl += c2;
    g_start[4 * t + 3] = excl; g_off[4 * t + 3] = excl;
}

__global__ void k_scatter() {
    int n = blockIdx.x * blockDim.x + threadIdx.x;
    if (n >= NPTS) return;
    int v = g_vox[n];
    int pos = atomicAdd(&g_off[v], 1);
    g_sorted[pos] = n;
}

// ---- packed fp32x2 helpers (FFMA2) ----
__device__ __forceinline__ u64 f2fma(u64 a, u64 b, u64 c) {
    u64 d;
    asm("fma.rn.f32x2 %0, %1, %2, %3;" : "=l"(d) : "l"(a), "l"(b), "l"(c));
    return d;
}
__device__ __forceinline__ u64 pk2(float v) {
    u64 r;
    asm("mov.b64 %0, {%1, %1};" : "=l"(r) : "f"(v));
    return r;
}
__device__ __forceinline__ float2 unpk(u64 p) {
    float2 f;
    asm("mov.b64 {%0, %1}, %2;" : "=f"(f.x), "=f"(f.y) : "l"(p));
    return f;
}
__device__ __forceinline__ void accP(u64* P, const float* wrow, u64 v2) {
    const ulonglong2* w = reinterpret_cast<const ulonglong2*>(wrow);
#pragma unroll
    for (int j = 0; j < 8; j++) {
        ulonglong2 ww = w[j];
        P[2 * j + 0] = f2fma(v2, ww.x, P[2 * j + 0]);
        P[2 * j + 1] = f2fma(v2, ww.y, P[2 * j + 1]);
    }
}
__device__ __forceinline__ void loadP(u64* P, const float* s) {
    const ulonglong2* b = reinterpret_cast<const ulonglong2*>(s);
#pragma unroll
    for (int j = 0; j < 8; j++) {
        ulonglong2 v = b[j];
        P[2 * j + 0] = v.x;
        P[2 * j + 1] = v.y;
    }
}
__device__ __forceinline__ void unpackRelu(const u64* P, float* H) {
#pragma unroll
    for (int j = 0; j < 16; j++) {
        float2 f = unpk(P[j]);
        H[2 * j + 0] = fmaxf(f.x, 0.f);
        H[2 * j + 1] = fmaxf(f.y, 0.f);
    }
}
__device__ __forceinline__ void unpackPlain(const u64* P, float* H) {
#pragma unroll
    for (int j = 0; j < 16; j++) {
        float2 f = unpk(P[j]);
        H[2 * j + 0] = f.x;
        H[2 * j + 1] = f.y;
    }
}

// ---- staging: (32 x C) row-major -> T[d*32+o] ----
// 16-row halves through a large scratch region (>= 16*C floats)
__device__ __forceinline__ void stage_odd16(const float* g, float* T, float* tmp,
                                            int tid, int C) {
    for (int h = 0; h < 2; h++) {
        const float4* g4 = reinterpret_cast<const float4*>(g + h * 16 * C);
        float4* t4 = reinterpret_cast<float4*>(tmp);
        int n4 = (16 * C) >> 2;
        for (int i = tid; i < n4; i += 64) t4[i] = g4[i];
        __syncthreads();
        for (int i = tid; i < 16 * C; i += 64) {
            int d = i >> 4, o = i & 15;
            T[d * 32 + h * 16 + o] = tmp[o * C + d];
        }
        __syncthreads();
    }
}
// 32x32, 16-row halves, padded rows (33) in scratch (needs >= 528 floats)
__device__ __forceinline__ void stage32_16(const float* g, float* T, float* tmp,
                                           int tid) {
    for (int h = 0; h < 2; h++) {
        const float* gh = g + h * 512;
        for (int i = tid; i < 512; i += 64)
            tmp[(i >> 5) * 33 + (i & 31)] = gh[i];
        __syncthreads();
        for (int i = tid; i < 512; i += 64) {
            int d = i >> 4, o = i & 15;
            T[d * 32 + h * 16 + o] = tmp[o * 33 + d];
        }
        __syncthreads();
    }
}
// 8-row chunks through small tmp (needs >= 8*C = 504 floats), for w0 staged last
__device__ __forceinline__ void stage_odd8(const float* g, float* T, float* tmp,
                                           int tid, int C) {
#pragma unroll
    for (int h = 0; h < 4; h++) {
        const float4* g4 = reinterpret_cast<const float4*>(g + h * 8 * C);
        float4* t4 = reinterpret_cast<float4*>(tmp);
        int n4 = (8 * C) >> 2;
        for (int i = tid; i < n4; i += 64) t4[i] = g4[i];
        __syncthreads();
        for (int i = tid; i < 8 * C; i += 64) {
            int d = i >> 3, o = i & 7;
            T[d * 32 + h * 8 + o] = tmp[o * C + d];
        }
        __syncthreads();
    }
}

// smem pool layout (floats)
#define OFF_W0T 0        // 2016
#define OFF_W1T 2016     // 1024
#define OFF_FT  3040     // 1024
#define OFF_VT  4064     // 1888
#define OFF_SM  5952     // 264
#define OFF_TMP 6216     // 504 (w0 staging only)
#define SP_TOT  6720     // 26880 bytes -> 8 blocks/SM when regs <= 128

__global__ void __launch_bounds__(64, 7) k_mlp(
    const float* __restrict__ pts, const float* __restrict__ vdirs,
    const float* __restrict__ w0, const float* __restrict__ b0,
    const float* __restrict__ w1, const float* __restrict__ b1,
    const float* __restrict__ fw, const float* __restrict__ fb,
    const float* __restrict__ sw, const float* __restrict__ sb,
    const float* __restrict__ vw, const float* __restrict__ vb,
    const float* __restrict__ rw, const float* __restrict__ rb,
    float* __restrict__ out)
{
    const int vox = blockIdx.x;
    const int tid = threadIdx.x;

    __shared__ __align__(16) float sp[SP_TOT];
    float* s_w0T = sp + OFF_W0T;   // [d=63][o=32]
    float* s_w1T = sp + OFF_W1T;   // [d=32][o=32]
    float* s_fT  = sp + OFF_FT;    // [d=32][o=32]
    float* s_vT  = sp + OFF_VT;    // [d=59][o=32]
    float* s_sm  = sp + OFF_SM;
    float* s_tmp = sp + OFF_TMP;

    const int start = g_start[vox];
    const int count = g_cnt[vox];

    // stage vT/w1T/fT first, borrowing the (still empty) w0T region as scratch;
    // stage w0T last through the small dedicated tmp
    stage_odd16(vw + (size_t)vox * 1888, s_vT, s_w0T, tid, 59);
    stage32_16(w1 + (size_t)vox * 1024, s_w1T, s_w0T, tid);
    stage32_16(fw + (size_t)vox * 1024, s_fT, s_w0T, tid);
    stage_odd8(w0 + (size_t)vox * 2016, s_w0T, s_tmp, tid, 63);

    for (int i = tid; i < 96; i += 64) {
        int c = i >> 5, d = i & 31;
        s_sm[160 + d * 3 + c] = rw[(size_t)vox * 96 + i];
    }
    if (tid < 32) {
        s_sm[tid]       = sw[(size_t)vox * 32 + tid];
        s_sm[32 + tid]  = b0[(size_t)vox * 32 + tid];
        s_sm[64 + tid]  = b1[(size_t)vox * 32 + tid];
        s_sm[96 + tid]  = fb[(size_t)vox * 32 + tid];
        s_sm[128 + tid] = vb[(size_t)vox * 32 + tid];
    }
    if (tid < 3) s_sm[256 + tid] = rb[(size_t)vox * 3 + tid];
    if (tid == 0) {
        s_sm[259] = sb[vox];
        g_cnt[vox] = 0;   // reset for next replay (count already read above)
    }
    __syncthreads();

    const int warp = tid >> 5, lane = tid & 31;

    // full 32-point tiles, warps alternate tiles (R2 structure)
    for (int base = warp * 32; base < count; base += 64) {
        const int i = base + lane;
        const bool act = (i < count);
        int n = 0;
        float px = 0.f, py = 0.f, pz = 0.f, dvx = 0.f, dvy = 0.f, dvz = 0.f;
        if (act) {
            n = g_sorted[start + i];
            px = pts[3 * n + 0]; py = pts[3 * n + 1]; pz = pts[3 * n + 2];
            int ray = n >> 7;   // N_SAMPLES = 128
            dvx = vdirs[3 * ray + 0]; dvy = vdirs[3 * ray + 1]; dvz = vdirs[3 * ray + 2];
        }

        u64 P[16];
        float A[32], B[32];

        // ---- layer0: 63 -> 32, relu ----
        loadP(P, s_sm + 32);
        accP(P, s_w0T + 0 * 32, pk2(px));
        accP(P, s_w0T + 1 * 32, pk2(py));
        accP(P, s_w0T + 2 * 32, pk2(pz));
        {
            float sx = __sinf(px), cx = __cosf(px);
            float sy = __sinf(py), cy = __cosf(py);
            float sz = __sinf(pz), cz = __cosf(pz);
#pragma unroll
            for (int k = 0; k < 10; k++) {
                const float* r = s_w0T + (3 + 6 * k) * 32;
                accP(P, r + 0 * 32, pk2(sx));
                accP(P, r + 1 * 32, pk2(sy));
                accP(P, r + 2 * 32, pk2(sz));
                accP(P, r + 3 * 32, pk2(cx));
                accP(P, r + 4 * 32, pk2(cy));
                accP(P, r + 5 * 32, pk2(cz));
                float t;
                t = 2.f * sx * cx; cx = 1.f - 2.f * sx * sx; sx = t;
                t = 2.f * sy * cy; cy = 1.f - 2.f * sy * sy; sy = t;
                t = 2.f * sz * cz; cz = 1.f - 2.f * sz * sz; sz = t;
            }
        }
        unpackRelu(P, A);

        // ---- layer1: 32 -> 32, relu ----
        loadP(P, s_sm + 64);
#pragma unroll
        for (int d = 0; d < 32; d++) accP(P, s_w1T + d * 32, pk2(A[d]));
        unpackRelu(P, B);

        // ---- sigma: 32 -> 1 ----
        float sg = s_sm[259];
#pragma unroll
        for (int d = 0; d < 32; d++) sg = fmaf(B[d], s_sm[d], sg);

        // ---- feat: 32 -> 32 (no relu) ----
        loadP(P, s_sm + 96);
#pragma unroll
        for (int d = 0; d < 32; d++) accP(P, s_fT + d * 32, pk2(B[d]));
        unpackPlain(P, A);

        // ---- view layer: concat(feat[32], ev[27]) -> 32, relu ----
        loadP(P, s_sm + 128);
#pragma unroll
        for (int d = 0; d < 32; d++) accP(P, s_vT + d * 32, pk2(A[d]));
        accP(P, s_vT + 32 * 32, pk2(dvx));
        accP(P, s_vT + 33 * 32, pk2(dvy));
        accP(P, s_vT + 34 * 32, pk2(dvz));
        {
            float sx = __sinf(dvx), cx = __cosf(dvx);
            float sy = __sinf(dvy), cy = __cosf(dvy);
            float sz = __sinf(dvz), cz = __cosf(dvz);
#pragma unroll
            for (int k = 0; k < 4; k++) {
                const float* r = s_vT + (35 + 6 * k) * 32;
                accP(P, r + 0 * 32, pk2(sx));
                accP(P, r + 1 * 32, pk2(sy));
                accP(P, r + 2 * 32, pk2(sz));
                accP(P, r + 3 * 32, pk2(cx));
                accP(P, r + 4 * 32, pk2(cy));
                accP(P, r + 5 * 32, pk2(cz));
                float t;
                t = 2.f * sx * cx; cx = 1.f - 2.f * sx * sx; sx = t;
                t = 2.f * sy * cy; cy = 1.f - 2.f * sy * sy; sy = t;
                t = 2.f * sz * cz; cz = 1.f - 2.f * sz * sz; sz = t;
            }
        }
        unpackRelu(P, B);

        // ---- rgb: 32 -> 3 ----
        float r0 = s_sm[256], r1 = s_sm[257], r2 = s_sm[258];
#pragma unroll
        for (int d = 0; d < 32; d++) {
            r0 = fmaf(B[d], s_sm[160 + d * 3 + 0], r0);
            r1 = fmaf(B[d], s_sm[160 + d * 3 + 1], r1);
            r2 = fmaf(B[d], s_sm[160 + d * 3 + 2], r2);
        }

        if (act) {
            out[3 * n + 0] = r0;
            out[3 * n + 1] = r1;
            out[3 * n + 2] = r2;
            out[(size_t)NPTS * 3 + n] = sg;
        }
    }
}

extern "C" void kernel_launch(void* const* d_in, const int* in_sizes, int n_in,
                              void* d_out, int out_size) {
    (void)in_sizes; (void)n_in; (void)out_size;
    const float* pts = (const float*)d_in[0];
    const float* vd  = (const float*)d_in[1];
    const float* w0  = (const float*)d_in[2];
    const float* b0  = (const float*)d_in[3];
    const float* w1  = (const float*)d_in[4];
    const float* b1  = (const float*)d_in[5];
    const float* fw  = (const float*)d_in[6];
    const float* fb  = (const float*)d_in[7];
    const float* sw  = (const float*)d_in[8];
    const float* sb  = (const float*)d_in[9];
    const float* vw  = (const float*)d_in[10];
    const float* vb  = (const float*)d_in[11];
    const float* rw  = (const float*)d_in[12];
    const float* rb  = (const float*)d_in[13];

    k_index<<<512, 256>>>(pts);
    k_scan<<<1, 1024>>>();
    k_scatter<<<512, 256>>>();
    k_mlp<<<NM, 64>>>(pts, vd, w0, b0, w1, b1, fw, fb, sw, sb, vw, vb, rw, rb,
                      (float*)d_out);
}